// round 1
// baseline (speedup 1.0000x reference)
#include <cuda_runtime.h>
#include <cuda_bf16.h>
#include <cstdint>
#include <float.h>

// Problem constants (RaggedTopKGatingModule: N=524288, E=64, K=8)
#define E_EXPERTS 64
#define TOPK 8
#define BLOCK_A 256
#define TOK_PER_THREAD 2
#define TOK_PER_BLOCK (BLOCK_A * TOK_PER_THREAD)       // 512
#define SLOTS_PER_CHUNK (TOK_PER_BLOCK * TOPK)         // 4096
#define ROUNDS (SLOTS_PER_CHUNK / BLOCK_A)             // 16
#define MAX_SLOTS (524288 * 8)
#define MAX_CHUNKS 2048

// Scratch (no allocation allowed; __device__ globals)
__device__ uint8_t  g_eids[MAX_SLOTS];        // 4 MB   expert id per slot
__device__ uint16_t g_lrank[MAX_SLOTS];       // 8 MB   within-chunk rank
__device__ int      g_chunk_hist[MAX_CHUNKS * E_EXPERTS];
__device__ int      g_chunk_base[MAX_CHUNKS * E_EXPERTS];

// ---------------------------------------------------------------------------
// Kernel A: top-8 + softmax + logits passthrough + ordered in-chunk ranking
// ---------------------------------------------------------------------------
__global__ __launch_bounds__(BLOCK_A, 2)
void topk_rank_kernel(const float* __restrict__ logits,
                      float* __restrict__ out_scores,
                      float* __restrict__ out_assign,
                      float* __restrict__ out_logits,
                      int n_tokens)
{
    __shared__ uint8_t sh_e[SLOTS_PER_CHUNK];       // 4 KB
    __shared__ int sh_wh[8 * E_EXPERTS];            // 2 KB per-warp hist
    __shared__ int sh_running[E_EXPERTS];           // 256 B

    const int tid  = threadIdx.x;
    const int lane = tid & 31;
    const int warp = tid >> 5;
    const int chunk = blockIdx.x;
    const int tok_base = chunk * TOK_PER_BLOCK;

    // -------- Phase 1: per-token top-8 + softmax --------
    #pragma unroll
    for (int it = 0; it < TOK_PER_THREAD; ++it) {
        const int lt = tid + it * BLOCK_A;          // block-local token
        const int t  = tok_base + lt;
        const float4* row  = (const float4*)(logits     + (size_t)t * E_EXPERTS);
        float4*       orow = (float4*)(out_logits + (size_t)t * E_EXPERTS);

        float v[E_EXPERTS];
        float tv[TOPK];
        int   ti[TOPK];
        #pragma unroll
        for (int k = 0; k < TOPK; ++k) { tv[k] = -FLT_MAX; ti[k] = 0; }

        #pragma unroll
        for (int j = 0; j < E_EXPERTS / 4; ++j) {
            float4 q = row[j];
            orow[j] = q;                            // fused pass-through copy
            float xs[4] = {q.x, q.y, q.z, q.w};
            #pragma unroll
            for (int u = 0; u < 4; ++u) {
                const int e = j * 4 + u;
                const float x = xs[u];
                v[e] = x;
                if (x > tv[TOPK - 1]) {             // strict: stable tie-break
                    tv[TOPK - 1] = x; ti[TOPK - 1] = e;
                    #pragma unroll
                    for (int jj = TOPK - 1; jj > 0; --jj) {
                        if (tv[jj] > tv[jj - 1]) {  // strict: keep lower idx first
                            float tf = tv[jj]; tv[jj] = tv[jj - 1]; tv[jj - 1] = tf;
                            int   tt = ti[jj]; ti[jj] = ti[jj - 1]; ti[jj - 1] = tt;
                        }
                    }
                }
            }
        }

        // softmax denominator; max == tv[0]
        const float mx = tv[0];
        float sum = 0.f;
        #pragma unroll
        for (int e = 0; e < E_EXPERTS; ++e) sum += __expf(v[e] - mx);
        const float inv = 1.0f / sum;

        float4 s0, s1;
        s0.x = __expf(tv[0] - mx) * inv;  s0.y = __expf(tv[1] - mx) * inv;
        s0.z = __expf(tv[2] - mx) * inv;  s0.w = __expf(tv[3] - mx) * inv;
        s1.x = __expf(tv[4] - mx) * inv;  s1.y = __expf(tv[5] - mx) * inv;
        s1.z = __expf(tv[6] - mx) * inv;  s1.w = __expf(tv[7] - mx) * inv;
        float4* srow = (float4*)(out_scores + (size_t)t * TOPK);
        srow[0] = s0; srow[1] = s1;

        #pragma unroll
        for (int k = 0; k < TOPK; ++k)
            sh_e[lt * TOPK + k] = (uint8_t)ti[k];
    }

    // init for ranking phase
    if (tid < E_EXPERTS) sh_running[tid] = 0;
    sh_wh[tid] = 0; sh_wh[tid + BLOCK_A] = 0;
    __syncthreads();

    // -------- Phase 2: ordered multisplit ranking over 4096 slots --------
    const size_t slot_base = (size_t)chunk * SLOTS_PER_CHUNK;
    for (int r = 0; r < ROUNDS; ++r) {
        const int slot = r * BLOCK_A + tid;         // token-major slot order
        const int e = sh_e[slot];

        unsigned mask = __match_any_sync(0xffffffffu, e);
        const int lrank = __popc(mask & ((1u << lane) - 1));
        const int leader = __ffs(mask) - 1;
        if (lane == leader) sh_wh[warp * E_EXPERTS + e] = __popc(mask);
        __syncthreads();

        int base = sh_running[e];
        #pragma unroll
        for (int w = 0; w < 8; ++w)
            if (w < warp) base += sh_wh[w * E_EXPERTS + e];
        const int rank = base + lrank;

        const size_t gslot = slot_base + slot;
        g_lrank[gslot] = (uint16_t)rank;
        g_eids[gslot]  = (uint8_t)e;
        out_assign[gslot] = (float)e;

        int addv = 0;
        if (tid < E_EXPERTS) {
            #pragma unroll
            for (int w = 0; w < 8; ++w) addv += sh_wh[w * E_EXPERTS + tid];
        }
        __syncthreads();                            // all reads of wh/running done
        if (tid < E_EXPERTS) sh_running[tid] += addv;
        sh_wh[tid] = 0; sh_wh[tid + BLOCK_A] = 0;   // zero for next round
        __syncthreads();
    }

    if (tid < E_EXPERTS)
        g_chunk_hist[chunk * E_EXPERTS + tid] = sh_running[tid];
}

// ---------------------------------------------------------------------------
// Kernel B: per-expert exclusive scan over chunk histograms + total counts
// grid = 64 (one expert per block), block = 1024 (one thread per chunk)
// ---------------------------------------------------------------------------
__global__ void scan_kernel(float* __restrict__ out_counts, int n_chunks)
{
    __shared__ int s[1024];
    const int e = blockIdx.x;
    const int c = threadIdx.x;

    int val = (c < n_chunks) ? g_chunk_hist[c * E_EXPERTS + e] : 0;
    s[c] = val;
    __syncthreads();

    // Hillis-Steele inclusive scan
    #pragma unroll
    for (int off = 1; off < 1024; off <<= 1) {
        int t = (c >= off) ? s[c - off] : 0;
        __syncthreads();
        s[c] += t;
        __syncthreads();
    }
    const int incl = s[c];
    if (c < n_chunks) g_chunk_base[c * E_EXPERTS + e] = incl - val;
    if (c == 1023) out_counts[e] = (float)incl;
}

// ---------------------------------------------------------------------------
// Kernel C: final offsets = chunk_base + local rank
// ---------------------------------------------------------------------------
__global__ void offsets_kernel(float* __restrict__ out_offs, int n_slots)
{
    const int idx = blockIdx.x * blockDim.x + threadIdx.x;
    if (idx < n_slots) {
        const int e = g_eids[idx];
        const int r = g_lrank[idx];
        const int chunk = idx >> 12;                // / SLOTS_PER_CHUNK (4096)
        out_offs[idx] = (float)(g_chunk_base[chunk * E_EXPERTS + e] + r);
    }
}

// ---------------------------------------------------------------------------
extern "C" void kernel_launch(void* const* d_in, const int* in_sizes, int n_in,
                              void* d_out, int out_size)
{
    // inputs: [0]=expert_counts(E), [1]=assignments(N*K), [2]=offsets(N*K), [3]=logits(N*E)
    const float* logits = (const float*)d_in[3];
    const int n_tokens = in_sizes[3] / E_EXPERTS;       // 524288
    const int n_slots  = n_tokens * TOPK;               // 4194304
    const int n_chunks = n_tokens / TOK_PER_BLOCK;      // 1024

    float* out = (float*)d_out;
    // layout: counts[E] | scores[N*K] | assign[N*K] | offs[N*K] | logits[N*E]
    float* out_counts = out;
    float* out_scores = out + E_EXPERTS;
    float* out_assign = out_scores + (size_t)n_slots;
    float* out_offs   = out_assign + (size_t)n_slots;
    float* out_logits = out_offs   + (size_t)n_slots;

    topk_rank_kernel<<<n_chunks, BLOCK_A>>>(logits, out_scores, out_assign,
                                            out_logits, n_tokens);
    scan_kernel<<<E_EXPERTS, 1024>>>(out_counts, n_chunks);
    offsets_kernel<<<(n_slots + 255) / 256, 256>>>(out_offs, n_slots);
}

// round 2
// speedup vs baseline: 1.5289x; 1.5289x over previous
#include <cuda_runtime.h>
#include <cuda_bf16.h>
#include <cstdint>
#include <float.h>

// Problem constants (RaggedTopKGatingModule: N=524288, E=64, K=8)
#define E_EXPERTS 64
#define TOPK 8
#define BLOCK_A 256
#define TOK_PER_BLOCK BLOCK_A                          // 256
#define SLOTS_PER_CHUNK (TOK_PER_BLOCK * TOPK)         // 2048
#define ROUNDS (SLOTS_PER_CHUNK / BLOCK_A)             // 8
#define MAX_SLOTS (524288 * 8)
#define MAX_CHUNKS 2048

// Scratch (no allocation allowed; __device__ globals)
__device__ uint8_t  g_eids[MAX_SLOTS];        // 4 MB   expert id per slot
__device__ uint16_t g_lrank[MAX_SLOTS];       // 8 MB   within-chunk rank
__device__ int      g_chunk_hist[MAX_CHUNKS * E_EXPERTS];
__device__ int      g_chunk_base[MAX_CHUNKS * E_EXPERTS];

// ---------------------------------------------------------------------------
// Kernel A: top-8 + online softmax + coalesced logits copy + in-chunk ranking
// ---------------------------------------------------------------------------
__global__ __launch_bounds__(BLOCK_A, 5)
void topk_rank_kernel(const float* __restrict__ logits,
                      float* __restrict__ out_scores,
                      float* __restrict__ out_assign,
                      float* __restrict__ out_logits,
                      int n_tokens)
{
    __shared__ uint8_t sh_e[SLOTS_PER_CHUNK];       // 2 KB
    __shared__ int sh_wh[8 * E_EXPERTS];            // 2 KB per-warp hist
    __shared__ int sh_running[E_EXPERTS];           // 256 B

    const int tid  = threadIdx.x;
    const int lane = tid & 31;
    const int warp = tid >> 5;
    const int chunk = blockIdx.x;
    const int tok_base = chunk * TOK_PER_BLOCK;

    // -------- Phase 0: coalesced pass-through copy of this chunk's logits ----
    // (warms L1 for the compute loads below; stores fully coalesced)
    {
        const size_t base = (size_t)tok_base * E_EXPERTS;
        const float4* src = (const float4*)(logits + base);
        float4*       dst = (float4*)(out_logits + base);
        const int n4 = TOK_PER_BLOCK * E_EXPERTS / 4;   // 4096 float4
        #pragma unroll
        for (int i = tid; i < n4; i += BLOCK_A)
            dst[i] = src[i];
    }

    // -------- Phase 1: per-token top-8 + online softmax --------
    {
        const int t = tok_base + tid;
        const float4* row = (const float4*)(logits + (size_t)t * E_EXPERTS);

        float tv[TOPK];
        int   ti[TOPK];
        #pragma unroll
        for (int k = 0; k < TOPK; ++k) { tv[k] = -FLT_MAX; ti[k] = 0; }

        float mx = -FLT_MAX;
        float sum = 0.f;

        #pragma unroll
        for (int j = 0; j < E_EXPERTS / 4; ++j) {
            float4 q = row[j];
            float xs[4] = {q.x, q.y, q.z, q.w};
            #pragma unroll
            for (int u = 0; u < 4; ++u) {
                const int e = j * 4 + u;
                const float x = xs[u];
                // online softmax accumulation
                if (x > mx) {
                    sum = sum * __expf(mx - x) + 1.0f;
                    mx = x;
                } else {
                    sum += __expf(x - mx);
                }
                // top-8 insertion (strict > preserves lowest-index tie-break)
                if (x > tv[TOPK - 1]) {
                    tv[TOPK - 1] = x; ti[TOPK - 1] = e;
                    #pragma unroll
                    for (int jj = TOPK - 1; jj > 0; --jj) {
                        if (tv[jj] > tv[jj - 1]) {
                            float tf = tv[jj]; tv[jj] = tv[jj - 1]; tv[jj - 1] = tf;
                            int   tt = ti[jj]; ti[jj] = ti[jj - 1]; ti[jj - 1] = tt;
                        }
                    }
                }
            }
        }

        const float inv = 1.0f / sum;       // mx == tv[0] (global max)
        float4 s0, s1;
        s0.x = __expf(tv[0] - mx) * inv;  s0.y = __expf(tv[1] - mx) * inv;
        s0.z = __expf(tv[2] - mx) * inv;  s0.w = __expf(tv[3] - mx) * inv;
        s1.x = __expf(tv[4] - mx) * inv;  s1.y = __expf(tv[5] - mx) * inv;
        s1.z = __expf(tv[6] - mx) * inv;  s1.w = __expf(tv[7] - mx) * inv;
        float4* srow = (float4*)(out_scores + (size_t)t * TOPK);
        srow[0] = s0; srow[1] = s1;

        #pragma unroll
        for (int k = 0; k < TOPK; ++k)
            sh_e[tid * TOPK + k] = (uint8_t)ti[k];
    }

    // init for ranking phase
    if (tid < E_EXPERTS) sh_running[tid] = 0;
    sh_wh[tid] = 0; sh_wh[tid + BLOCK_A] = 0;
    __syncthreads();

    // -------- Phase 2: ordered multisplit ranking over 2048 slots --------
    const size_t slot_base = (size_t)chunk * SLOTS_PER_CHUNK;
    for (int r = 0; r < ROUNDS; ++r) {
        const int slot = r * BLOCK_A + tid;         // token-major slot order
        const int e = sh_e[slot];

        unsigned mask = __match_any_sync(0xffffffffu, e);
        const int lrank = __popc(mask & ((1u << lane) - 1));
        const int leader = __ffs(mask) - 1;
        if (lane == leader) sh_wh[warp * E_EXPERTS + e] = __popc(mask);
        __syncthreads();

        int base = sh_running[e];
        #pragma unroll
        for (int w = 0; w < 8; ++w)
            if (w < warp) base += sh_wh[w * E_EXPERTS + e];
        const int rank = base + lrank;

        const size_t gslot = slot_base + slot;
        g_lrank[gslot] = (uint16_t)rank;
        g_eids[gslot]  = (uint8_t)e;
        out_assign[gslot] = (float)e;

        int addv = 0;
        if (tid < E_EXPERTS) {
            #pragma unroll
            for (int w = 0; w < 8; ++w) addv += sh_wh[w * E_EXPERTS + tid];
        }
        __syncthreads();                            // all reads of wh/running done
        if (tid < E_EXPERTS) sh_running[tid] += addv;
        sh_wh[tid] = 0; sh_wh[tid + BLOCK_A] = 0;   // zero for next round
        __syncthreads();
    }

    if (tid < E_EXPERTS)
        g_chunk_hist[chunk * E_EXPERTS + tid] = sh_running[tid];
}

// ---------------------------------------------------------------------------
// Kernel B: per-expert exclusive scan over 2048 chunk histograms (2 per thread)
// grid = 64 (one expert per block), block = 1024
// ---------------------------------------------------------------------------
__global__ void scan_kernel(float* __restrict__ out_counts, int n_chunks)
{
    __shared__ int s[1024];
    const int e = blockIdx.x;
    const int c = threadIdx.x;

    const int c0 = 2 * c, c1 = 2 * c + 1;
    int a = (c0 < n_chunks) ? g_chunk_hist[c0 * E_EXPERTS + e] : 0;
    int b = (c1 < n_chunks) ? g_chunk_hist[c1 * E_EXPERTS + e] : 0;
    int pair = a + b;
    s[c] = pair;
    __syncthreads();

    // Hillis-Steele inclusive scan over pair sums
    #pragma unroll
    for (int off = 1; off < 1024; off <<= 1) {
        int t = (c >= off) ? s[c - off] : 0;
        __syncthreads();
        s[c] += t;
        __syncthreads();
    }
    const int incl = s[c];
    const int excl = incl - pair;
    if (c0 < n_chunks) g_chunk_base[c0 * E_EXPERTS + e] = excl;
    if (c1 < n_chunks) g_chunk_base[c1 * E_EXPERTS + e] = excl + a;
    if (c == 1023) out_counts[e] = (float)incl;
}

// ---------------------------------------------------------------------------
// Kernel C: final offsets = chunk_base + local rank
// ---------------------------------------------------------------------------
__global__ void offsets_kernel(float* __restrict__ out_offs, int n_slots)
{
    const int idx = blockIdx.x * blockDim.x + threadIdx.x;
    if (idx < n_slots) {
        const int e = g_eids[idx];
        const int r = g_lrank[idx];
        const int chunk = idx >> 11;                // / SLOTS_PER_CHUNK (2048)
        out_offs[idx] = (float)(g_chunk_base[chunk * E_EXPERTS + e] + r);
    }
}

// ---------------------------------------------------------------------------
extern "C" void kernel_launch(void* const* d_in, const int* in_sizes, int n_in,
                              void* d_out, int out_size)
{
    // inputs: [0]=expert_counts(E), [1]=assignments(N*K), [2]=offsets(N*K), [3]=logits(N*E)
    const float* logits = (const float*)d_in[3];
    const int n_tokens = in_sizes[3] / E_EXPERTS;       // 524288
    const int n_slots  = n_tokens * TOPK;               // 4194304
    const int n_chunks = n_tokens / TOK_PER_BLOCK;      // 2048

    float* out = (float*)d_out;
    // layout: counts[E] | scores[N*K] | assign[N*K] | offs[N*K] | logits[N*E]
    float* out_counts = out;
    float* out_scores = out + E_EXPERTS;
    float* out_assign = out_scores + (size_t)n_slots;
    float* out_offs   = out_assign + (size_t)n_slots;
    float* out_logits = out_offs   + (size_t)n_slots;

    topk_rank_kernel<<<n_chunks, BLOCK_A>>>(logits, out_scores, out_assign,
                                            out_logits, n_tokens);
    scan_kernel<<<E_EXPERTS, 1024>>>(out_counts, n_chunks);
    offsets_kernel<<<(n_slots + 255) / 256, 256>>>(out_offs, n_slots);
}